// round 17
// baseline (speedup 1.0000x reference)
#include <cuda_runtime.h>
#include <cuda_fp16.h>
#include <cstdint>
#include <cstddef>

#define NTOK   16384
#define DMODEL 1024
#define HDIM   4096
#define NEXP   8
#define MAXT   136
#define BM     128
#define BK     64
#define ASTR   72                    // A smem stride (halves): 144B rows, conflict-free
#define BSTR   136                   // B smem stride (halves): 272B rows, conflict-free trans
#define ATILE  (BM * ASTR)           // 9216 halves
#define BTILE  (BK * BSTR)           // 8704 halves
#define ABYTES (ATILE * 2)           // 18432 B
#define STAGEB (ABYTES + BTILE * 2)  // 35840 B
#define NSTG   3
#define DYN_SMEM (NSTG * STAGEB)     // 107520 B
#define NPERS  296                   // persistent CTAs (2 per SM x 148 SMs)

// ------------------------- device scratch -------------------------
__device__ __half g_Wp16[(size_t)NEXP * DMODEL * 2 * HDIM]; // [E][D][2H] natural, half
__device__ __half g_Wo16[(size_t)NEXP * HDIM * DMODEL];     // [E][H][D]
__device__ __half g_act[(size_t)NTOK * HDIM];
__device__ __half g_xg [(size_t)NTOK * DMODEL];
__device__ int    g_perm[NTOK];
__device__ int    g_tile_e[MAXT], g_tile_row[MAXT], g_tile_mr[MAXT];
__device__ int    g_ntiles;

// ------------------------- helpers -------------------------
__device__ __forceinline__ uint32_t smem_u32(const void* p) {
    uint32_t a;
    asm("{ .reg .u64 t; cvta.to.shared.u64 t, %1; cvt.u32.u64 %0, t; }" : "=r"(a) : "l"(p));
    return a;
}
__device__ __forceinline__ void cp16(uint32_t dst, const void* src, uint32_t sz) {
    asm volatile("cp.async.cg.shared.global [%0], [%1], 16, %2;" :: "r"(dst), "l"(src), "r"(sz));
}
#define CP_COMMIT() asm volatile("cp.async.commit_group;" ::: "memory")
template <int W> __device__ __forceinline__ void cp_wait() {
    asm volatile("cp.async.wait_group %0;" :: "n"(W) : "memory");
}
__device__ __forceinline__ void ldm4(uint32_t* r, uint32_t addr) {
    asm volatile("ldmatrix.sync.aligned.m8n8.x4.shared.b16 {%0,%1,%2,%3}, [%4];"
                 : "=r"(r[0]), "=r"(r[1]), "=r"(r[2]), "=r"(r[3]) : "r"(addr));
}
__device__ __forceinline__ void ldm4t(uint32_t* r, uint32_t addr) {
    asm volatile("ldmatrix.sync.aligned.m8n8.x4.trans.shared.b16 {%0,%1,%2,%3}, [%4];"
                 : "=r"(r[0]), "=r"(r[1]), "=r"(r[2]), "=r"(r[3]) : "r"(addr));
}
__device__ __forceinline__ void mma16(float* c, const uint32_t* a, const uint32_t* b) {
    asm("mma.sync.aligned.m16n8k16.row.col.f32.f16.f16.f32 "
        "{%0,%1,%2,%3},{%4,%5,%6,%7},{%8,%9},{%0,%1,%2,%3};"
        : "+f"(c[0]), "+f"(c[1]), "+f"(c[2]), "+f"(c[3])
        : "r"(a[0]), "r"(a[1]), "r"(a[2]), "r"(a[3]), "r"(b[0]), "r"(b[1]));
}

// ------------------------- scheduling -------------------------
__global__ void k_sched(const int* __restrict__ at) {
    __shared__ int sc[NEXP], so[NEXP], scur[NEXP];
    int tid = threadIdx.x;
    if (tid < NEXP) { sc[tid] = 0; scur[tid] = 0; }
    __syncthreads();
    for (int i = tid; i < NTOK; i += 256) atomicAdd(&sc[at[i]], 1);
    __syncthreads();
    if (tid == 0) {
        int o = 0, t = 0;
        for (int e = 0; e < NEXP; e++) {
            so[e] = o;
            for (int r = 0; r < sc[e]; r += BM) {
                g_tile_e[t] = e; g_tile_row[t] = o + r;
                g_tile_mr[t] = min(BM, sc[e] - r); t++;
            }
            o += sc[e];
        }
        g_ntiles = t;
    }
    __syncthreads();
    for (int i = tid; i < NTOK; i += 256) {
        int e = at[i];
        g_perm[so[e] + atomicAdd(&scur[e], 1)] = i;
    }
}

__global__ void k_gather(const float* __restrict__ x) {
    int p = blockIdx.x;
    int r = g_perm[p];
    float4 v = *(const float4*)&x[(size_t)r * DMODEL + threadIdx.x * 4];
    __half2 h01 = __floats2half2_rn(v.x, v.y);
    __half2 h23 = __floats2half2_rn(v.z, v.w);
    uint2 u;
    u.x = *(uint32_t*)&h01; u.y = *(uint32_t*)&h23;
    *(uint2*)&g_xg[(size_t)p * DMODEL + threadIdx.x * 4] = u;
}

__global__ void k_cvt(const float4* __restrict__ in, uint2* __restrict__ out, int n4) {
    int i = blockIdx.x * 256 + threadIdx.x;
    if (i < n4) {
        float4 v = in[i];
        __half2 a = __floats2half2_rn(v.x, v.y);
        __half2 b = __floats2half2_rn(v.z, v.w);
        uint2 u;
        u.x = *(uint32_t*)&a; u.y = *(uint32_t*)&b;
        out[i] = u;
    }
}

// ======================= GEMM1 (persistent, cross-tile pipelined) =======================
// act = swishglu(xg @ Wp + bp). 296 CTAs; items w: t = w/64, nb = w%64 (tail-contiguous).
// Per CTA: 128x128 tile, 8 warps (2m x 4n, warp 64x32), NKT=16 chunks/item.
// 3-stage cp.async ring never drains across item boundaries.
#define G1_NKT (DMODEL / BK)   // 16

__global__ void __launch_bounds__(256, 2) k_gemm1(const float* __restrict__ bp) {
    extern __shared__ __half smh[];
    const int tid = threadIdx.x, lane = tid & 31, warp = tid >> 5;
    const int wm = warp >> 2, wn = warp & 3;
    const int ntiles = g_ntiles;
    const int NI = ntiles * 64;
    const int stride = gridDim.x;
    const uint32_t smb = smem_u32(smh);

    uint32_t aoff[4], boff[2];
    #pragma unroll
    for (int i = 0; i < 4; i++)
        aoff[i] = ((wm * 64 + i * 16 + (lane & 15)) * ASTR + (lane >> 4) * 8) * 2;
    boff[0] = ABYTES + ((lane & 15) * BSTR + wn * 16 + (lane >> 4) * 8) * 2;
    boff[1] = ABYTES + ((lane & 15) * BSTR + 64 + wn * 16 + (lane >> 4) * 8) * 2;

    auto load = [&](int Lc, int w, int kt) {
        int t = w >> 6, nb = w & 63;
        int e = g_tile_e[t], row0 = g_tile_row[t];
        const __half* Ag = g_xg + (size_t)row0 * DMODEL;
        const __half* BA = g_Wp16 + (size_t)e * DMODEL * 2 * HDIM + nb * 64;
        const __half* BB = BA + HDIM;
        uint32_t sb = smb + (Lc % NSTG) * STAGEB;
        int k0 = kt * BK;
        #pragma unroll
        for (int i = 0; i < 8; i++) {
            int idx = tid + i * 256;
            if (idx < 1024) {                       // A: 128 rows x 64k
                int r = idx >> 3, c = (idx & 7) * 8;
                cp16(sb + (r * ASTR + c) * 2, Ag + (size_t)r * DMODEL + k0 + c,
                     (row0 + r) < NTOK ? 16u : 0u);
            } else {                                // B: 64 k-rows x 128n
                int j = idx - 1024;
                int k = j >> 4, c = j & 15;
                const __half* src = (c < 8)
                    ? BA + (size_t)(k0 + k) * (2 * HDIM) + c * 8
                    : BB + (size_t)(k0 + k) * (2 * HDIM) + (c - 8) * 8;
                cp16(sb + ABYTES + (k * BSTR + c * 8) * 2, src, 16u);
            }
        }
        CP_COMMIT();
    };

    int wl = blockIdx.x, ktl = 0;      // load cursor
    int wc = blockIdx.x, ktc = 0;      // compute cursor
    int Lc = 0, Cc = 0;                // chunks loaded / computed
    if (wc >= NI) return;

    for (int p = 0; p < 2 && wl < NI; p++) {
        load(Lc, wl, ktl); Lc++;
        if (++ktl == G1_NKT) { ktl = 0; wl += stride; }
    }

    float acc[4][4][4] = {};
    while (wc < NI) {
        if (Lc - Cc >= 2) cp_wait<1>(); else cp_wait<0>();
        __syncthreads();
        if (wl < NI) {
            load(Lc, wl, ktl); Lc++;
            if (++ktl == G1_NKT) { ktl = 0; wl += stride; }
        }
        uint32_t sb = smb + (Cc % NSTG) * STAGEB;
        #pragma unroll
        for (int ks = 0; ks < 4; ks++) {
            uint32_t a[4][4], b[2][4];
            #pragma unroll
            for (int i = 0; i < 4; i++) ldm4(a[i], sb + aoff[i] + ks * 32);
            #pragma unroll
            for (int jj = 0; jj < 2; jj++) ldm4t(b[jj], sb + boff[jj] + ks * 16 * BSTR * 2);
            #pragma unroll
            for (int i = 0; i < 4; i++)
                #pragma unroll
                for (int jj = 0; jj < 2; jj++) {
                    mma16(acc[i][2 * jj],     a[i], &b[jj][0]);
                    mma16(acc[i][2 * jj + 1], a[i], &b[jj][2]);
                }
        }
        Cc++;
        if (++ktc == G1_NKT) {
            int t = wc >> 6, nb = wc & 63;
            int e = g_tile_e[t], row0 = g_tile_row[t], mrows = g_tile_mr[t];
            const float* bpe = bp + (size_t)e * 2 * HDIM + nb * 64;
            const float* bge = bpe + HDIM;
            #pragma unroll
            for (int i = 0; i < 4; i++) {
                int rb = wm * 64 + i * 16 + (lane >> 2);
                #pragma unroll
                for (int jn = 0; jn < 2; jn++) {
                    int hl = wn * 16 + jn * 8 + (lane & 3) * 2;
                    float bp0 = bpe[hl], bp1 = bpe[hl + 1];
                    float bg0 = bge[hl], bg1 = bge[hl + 1];
                    #pragma unroll
                    for (int c = 0; c < 2; c++) {
                        int r = rb + c * 8;
                        if (r >= mrows) continue;
                        float p0 = acc[i][jn][c * 2 + 0] + bp0;
                        float p1 = acc[i][jn][c * 2 + 1] + bp1;
                        float g0 = acc[i][jn + 2][c * 2 + 0] + bg0;
                        float g1 = acc[i][jn + 2][c * 2 + 1] + bg1;
                        float a0 = p0 * (g0 / (1.f + __expf(-g0)));
                        float a1 = p1 * (g1 / (1.f + __expf(-g1)));
                        __half2 hv = __floats2half2_rn(a0, a1);
                        *(__half2*)&g_act[(size_t)(row0 + r) * HDIM + nb * 64 + hl] = hv;
                    }
                }
            }
            #pragma unroll
            for (int i = 0; i < 4; i++)
                #pragma unroll
                for (int j = 0; j < 4; j++)
                    #pragma unroll
                    for (int c = 0; c < 4; c++) acc[i][j][c] = 0.f;
            ktc = 0; wc += stride;
        }
    }
}

// ======================= GEMM2 (persistent, cross-tile pipelined) =======================
// out[perm] = x + act @ Wo + bo. Items w: t = w/8, nb = w%8. NKT=64 chunks/item.
#define G2_NKT (HDIM / BK)   // 64

__global__ void __launch_bounds__(256, 2) k_gemm2(const float* __restrict__ x,
                                                  const float* __restrict__ bo,
                                                  float* __restrict__ out) {
    extern __shared__ __half smh[];
    const int tid = threadIdx.x, lane = tid & 31, warp = tid >> 5;
    const int wm = warp >> 2, wn = warp & 3;
    const int ntiles = g_ntiles;
    const int NI = ntiles * 8;
    const int stride = gridDim.x;
    const uint32_t smb = smem_u32(smh);

    uint32_t aoff[4], boff[2];
    #pragma unroll
    for (int i = 0; i < 4; i++)
        aoff[i] = ((wm * 64 + i * 16 + (lane & 15)) * ASTR + (lane >> 4) * 8) * 2;
    boff[0] = ABYTES + ((lane & 15) * BSTR + wn * 32 + (lane >> 4) * 8) * 2;
    boff[1] = ABYTES + ((lane & 15) * BSTR + wn * 32 + 16 + (lane >> 4) * 8) * 2;

    auto load = [&](int Lc, int w, int kt) {
        int t = w >> 3, nb = w & 7;
        int e = g_tile_e[t], row0 = g_tile_row[t];
        const __half* Ag = g_act + (size_t)row0 * HDIM;
        const __half* BA = g_Wo16 + (size_t)e * HDIM * DMODEL + nb * 128;
        const __half* BB = BA + 64;
        uint32_t sb = smb + (Lc % NSTG) * STAGEB;
        int k0 = kt * BK;
        #pragma unroll
        for (int i = 0; i < 8; i++) {
            int idx = tid + i * 256;
            if (idx < 1024) {
                int r = idx >> 3, c = (idx & 7) * 8;
                cp16(sb + (r * ASTR + c) * 2, Ag + (size_t)r * HDIM + k0 + c,
                     (row0 + r) < NTOK ? 16u : 0u);
            } else {
                int j = idx - 1024;
                int k = j >> 4, c = j & 15;
                const __half* src = (c < 8)
                    ? BA + (size_t)(k0 + k) * DMODEL + c * 8
                    : BB + (size_t)(k0 + k) * DMODEL + (c - 8) * 8;
                cp16(sb + ABYTES + (k * BSTR + c * 8) * 2, src, 16u);
            }
        }
        CP_COMMIT();
    };

    int wl = blockIdx.x, ktl = 0;
    int wc = blockIdx.x, ktc = 0;
    int Lc = 0, Cc = 0;
    if (wc >= NI) return;

    for (int p = 0; p < 2 && wl < NI; p++) {
        load(Lc, wl, ktl); Lc++;
        if (++ktl == G2_NKT) { ktl = 0; wl += stride; }
    }

    float acc[4][4][4] = {};
    while (wc < NI) {
        if (Lc - Cc >= 2) cp_wait<1>(); else cp_wait<0>();
        __syncthreads();
        if (wl < NI) {
            load(Lc, wl, ktl); Lc++;
            if (++ktl == G2_NKT) { ktl = 0; wl += stride; }
        }
        uint32_t sb = smb + (Cc % NSTG) * STAGEB;
        #pragma unroll
        for (int ks = 0; ks < 4; ks++) {
            uint32_t a[4][4], b[2][4];
            #pragma unroll
            for (int i = 0; i < 4; i++) ldm4(a[i], sb + aoff[i] + ks * 32);
            #pragma unroll
            for (int jj = 0; jj < 2; jj++) ldm4t(b[jj], sb + boff[jj] + ks * 16 * BSTR * 2);
            #pragma unroll
            for (int i = 0; i < 4; i++)
                #pragma unroll
                for (int jj = 0; jj < 2; jj++) {
                    mma16(acc[i][2 * jj],     a[i], &b[jj][0]);
                    mma16(acc[i][2 * jj + 1], a[i], &b[jj][2]);
                }
        }
        Cc++;
        if (++ktc == G2_NKT) {
            int t = wc >> 3, nb = wc & 7;
            int e = g_tile_e[t], row0 = g_tile_row[t], mrows = g_tile_mr[t];
            const float* boe = bo + (size_t)e * DMODEL + nb * 128;
            #pragma unroll
            for (int i = 0; i < 4; i++) {
                int rb = wm * 64 + i * 16 + (lane >> 2);
                #pragma unroll
                for (int h = 0; h < 2; h++) {
                    int r = rb + h * 8;
                    if (r >= mrows) continue;
                    int orow = g_perm[row0 + r];
                    #pragma unroll
                    for (int j = 0; j < 4; j++) {
                        int cl = wn * 32 + j * 8 + (lane & 3) * 2;
                        int cg = nb * 128 + cl;
                        float2 xv = *(const float2*)&x[(size_t)orow * DMODEL + cg];
                        float2 v;
                        v.x = acc[i][j][h * 2 + 0] + boe[cl]     + xv.x;
                        v.y = acc[i][j][h * 2 + 1] + boe[cl + 1] + xv.y;
                        *(float2*)&out[(size_t)orow * DMODEL + cg] = v;
                    }
                }
            }
            #pragma unroll
            for (int i = 0; i < 4; i++)
                #pragma unroll
                for (int j = 0; j < 4; j++)
                    #pragma unroll
                    for (int c = 0; c < 4; c++) acc[i][j][c] = 0.f;
            ktc = 0; wc += stride;
        }
    }
}

// ------------------------- RMSNorm -------------------------
__global__ void k_rms(float* __restrict__ out, const float* __restrict__ nw) {
    int row = blockIdx.x, t = threadIdx.x;
    float4 v = *(float4*)&out[(size_t)row * DMODEL + t * 4];
    float ss = v.x * v.x + v.y * v.y + v.z * v.z + v.w * v.w;
    #pragma unroll
    for (int o = 16; o; o >>= 1) ss += __shfl_xor_sync(0xFFFFFFFFu, ss, o);
    __shared__ float ws[8];
    if ((t & 31) == 0) ws[t >> 5] = ss;
    __syncthreads();
    float tot = ws[0] + ws[1] + ws[2] + ws[3] + ws[4] + ws[5] + ws[6] + ws[7];
    float s = rsqrtf(tot / DMODEL + 1e-6f);
    float4 w = *(const float4*)&nw[t * 4];
    v.x *= s * w.x; v.y *= s * w.y; v.z *= s * w.z; v.w *= s * w.w;
    *(float4*)&out[(size_t)row * DMODEL + t * 4] = v;
}

// ------------------------- launch -------------------------
extern "C" void kernel_launch(void* const* d_in, const int* in_sizes, int n_in,
                              void* d_out, int out_size) {
    const float* x  = (const float*)d_in[0];
    const int*   at = (const int*)d_in[1];
    const float* Wp = (const float*)d_in[2];
    const float* bp = (const float*)d_in[3];
    const float* Wo = (const float*)d_in[4];
    const float* bo = (const float*)d_in[5];
    const float* nw = (const float*)d_in[6];
    float* out = (float*)d_out;

    static bool attr_set = false;
    if (!attr_set) {
        cudaFuncSetAttribute(k_gemm1, cudaFuncAttributeMaxDynamicSharedMemorySize, DYN_SMEM);
        cudaFuncSetAttribute(k_gemm2, cudaFuncAttributeMaxDynamicSharedMemorySize, DYN_SMEM);
        attr_set = true;
    }

    __half* wp16; cudaGetSymbolAddress((void**)&wp16, g_Wp16);
    __half* wo16; cudaGetSymbolAddress((void**)&wo16, g_Wo16);
    const int np4 = NEXP * DMODEL * 2 * HDIM / 4;
    const int no4 = NEXP * HDIM * DMODEL / 4;

    // order keeps k_gemm1 at the empirically-profiled 4th slot
    k_sched<<<1, 256>>>(at);                                            // 1
    k_gather<<<NTOK, 256>>>(x);                                         // 2
    k_cvt<<<(np4 + 255) / 256, 256>>>((const float4*)Wp, (uint2*)wp16, np4);  // 3
    k_gemm1<<<NPERS, 256, DYN_SMEM>>>(bp);                              // 4
    k_cvt<<<(no4 + 255) / 256, 256>>>((const float4*)Wo, (uint2*)wo16, no4);  // 5
    k_gemm2<<<NPERS, 256, DYN_SMEM>>>(x, bo, out);                      // 6
    k_rms<<<NTOK, 256>>>(out, nw);                                      // 7
}